// round 16
// baseline (speedup 1.0000x reference)
#include <cuda_runtime.h>
#include <cuda_bf16.h>
#include <math.h>
#include <stdint.h>

#define ALPHA 0.2f
#define NEGV  -9000000000000000.0f

#define S_    2048
#define WK    32
#define DD    5
#define FF    16
#define HH    128
#define EE    128
#define NSEC  16
#define NSEQ1 (S_*WK)      /* 65536 */
#define G3    384

// ---------------- scratch (device globals; no allocation) ----------------
__device__ float g_short[NSEQ1 * HH];
__device__ float g_Wh[S_ * EE];
__device__ float g_s1[S_];
__device__ float g_s2[S_];
__device__ float g_intra[S_ * EE];
__device__ float g_gig[S_ * G3];
__device__ float g_lg[S_ * EE];
__device__ float g_la[S_ * EE];
__device__ float g_sec[NSEC * EE];
__device__ float g_secout[NSEC * EE];
__device__ int   g_secmem[S_];
__device__ int   g_secoff[NSEC + 1];

// packed bf16 weights (u32 = 2 bf16 along k)
__device__ uint32_t g_pb1rz[256 * 72];   // gru1 [Whh|Wih] for r,z  (k=144)
__device__ uint32_t g_pb1n [128 * 64];   // gru1 Whh_n (k=128)
__device__ uint32_t g_pb1xn[128 * 8];    // gru1 Wih_n (k=16)
__device__ float    g_b1rz[256], g_b1nn[128], g_b1in[128];

__device__ uint32_t g_pbarz[256 * 128];  // la [Whh|Wih] for r,z (k=256)
__device__ uint32_t g_pban [128 * 64];   // la Whh_n (k=128)
__device__ uint32_t g_paxn [128 * 64];   // la Wih_n (k=128)
__device__ float    g_barz[256], g_bann[128], g_bain[128];

__device__ __forceinline__ float sigf(float x) { return 1.f / (1.f + expf(-x)); }
__device__ __forceinline__ float tanh_ap(float x) {
    float y; asm("tanh.approx.f32 %0, %1;" : "=f"(y) : "f"(x)); return y;
}
__device__ __forceinline__ float sig_ap(float x) {
    return 0.5f * tanh_ap(0.5f * x) + 0.5f;
}
__device__ __forceinline__ uint32_t packbf(float a, float b) {
    __nv_bfloat162 t = __floats2bfloat162_rn(a, b);
    return *reinterpret_cast<uint32_t*>(&t);
}
__device__ __forceinline__ float tf32r(float x) {
    uint32_t u;
    asm("cvt.rna.tf32.f32 %0, %1;" : "=r"(u) : "f"(x));
    return __uint_as_float(u);
}
__device__ __forceinline__ void mma8(float* d, const float* a, const float* b) {
    asm volatile(
        "mma.sync.aligned.m16n8k8.row.col.f32.tf32.tf32.f32 "
        "{%0,%1,%2,%3}, {%4,%5,%6,%7}, {%8,%9}, {%0,%1,%2,%3};\n"
        : "+f"(d[0]), "+f"(d[1]), "+f"(d[2]), "+f"(d[3])
        : "r"(__float_as_uint(a[0])), "r"(__float_as_uint(a[1])),
          "r"(__float_as_uint(a[2])), "r"(__float_as_uint(a[3])),
          "r"(__float_as_uint(b[0])), "r"(__float_as_uint(b[1])));
}
__device__ __forceinline__ void mma16(float* d, const uint32_t* a,
                                      uint32_t b0, uint32_t b1) {
    asm volatile(
        "mma.sync.aligned.m16n8k16.row.col.f32.bf16.bf16.f32 "
        "{%0,%1,%2,%3}, {%4,%5,%6,%7}, {%8,%9}, {%0,%1,%2,%3};\n"
        : "+f"(d[0]), "+f"(d[1]), "+f"(d[2]), "+f"(d[3])
        : "r"(a[0]), "r"(a[1]), "r"(a[2]), "r"(a[3]), "r"(b0), "r"(b1));
}
__device__ __forceinline__ float4 cvt4(float4 v) {
    v.x = tf32r(v.x); v.y = tf32r(v.y); v.z = tf32r(v.z); v.w = tf32r(v.w);
    return v;
}
__device__ __forceinline__ uint32_t smem_u32(const void* p) {
    return (uint32_t)__cvta_generic_to_shared(p);
}
__device__ __forceinline__ void ldsm4(uint32_t* r, uint32_t addr) {
    asm volatile("ldmatrix.sync.aligned.m8n8.x4.shared.b16 {%0,%1,%2,%3}, [%4];"
        : "=r"(r[0]), "=r"(r[1]), "=r"(r[2]), "=r"(r[3]) : "r"(addr));
}
__device__ __forceinline__ void ldsm2(uint32_t* r, uint32_t addr) {
    asm volatile("ldmatrix.sync.aligned.m8n8.x2.shared.b16 {%0,%1}, [%2];"
        : "=r"(r[0]), "=r"(r[1]) : "r"(addr));
}

// smem strides (u32 words) — multiples of 4 (16B ldmatrix alignment),
// mod 32 in {4,12} => conflict-free 8-row LDSM phases.
#define BRZS1 76
#define BNS1  68
#define BXS1  12
#define PAS1  76
#define BRZSA 132
#define BNSA  68
#define PASA  132

// ---------------- weight prep ------------------------------------------------
__global__ void __launch_bounds__(256) prep1(
    const float* __restrict__ Whh, const float* __restrict__ Wih,
    const float* __restrict__ bih, const float* __restrict__ bhh)
{
    int idx = blockIdx.x * 256 + threadIdx.x;
    if (idx < 256 * 72) {
        int n = idx / 72, i = idx % 72, k = 2 * i;
        float a, b;
        if (k < 128) { a = Whh[n * 128 + k]; b = Whh[n * 128 + k + 1]; }
        else         { a = Wih[n * 16 + k - 128]; b = Wih[n * 16 + k - 127]; }
        g_pb1rz[idx] = packbf(a, b);
    }
    if (idx < 128 * 64) {
        int j = idx / 64, i = idx % 64;
        g_pb1n[idx] = packbf(Whh[(256 + j) * 128 + 2 * i],
                             Whh[(256 + j) * 128 + 2 * i + 1]);
    }
    if (idx < 128 * 8) {
        int j = idx / 8, i = idx % 8;
        g_pb1xn[idx] = packbf(Wih[(256 + j) * 16 + 2 * i],
                              Wih[(256 + j) * 16 + 2 * i + 1]);
    }
    if (idx < 256) g_b1rz[idx] = bih[idx] + bhh[idx];
    if (idx < 128) { g_b1nn[idx] = bhh[256 + idx]; g_b1in[idx] = bih[256 + idx]; }
}

__global__ void __launch_bounds__(256) prepa(
    const float* __restrict__ Whh, const float* __restrict__ Wih,
    const float* __restrict__ bih, const float* __restrict__ bhh)
{
    int idx = blockIdx.x * 256 + threadIdx.x;
    if (idx < 256 * 128) {
        int n = idx / 128, i = idx % 128, k = 2 * i;
        float a, b;
        if (k < 128) { a = Whh[n * 128 + k]; b = Whh[n * 128 + k + 1]; }
        else         { a = Wih[n * 128 + k - 128]; b = Wih[n * 128 + k - 127]; }
        g_pbarz[idx] = packbf(a, b);
    }
    if (idx < 128 * 64) {
        int j = idx / 64, i = idx % 64;
        g_pban[idx] = packbf(Whh[(256 + j) * 128 + 2 * i],
                             Whh[(256 + j) * 128 + 2 * i + 1]);
        g_paxn[idx] = packbf(Wih[(256 + j) * 128 + 2 * i],
                             Wih[(256 + j) * 128 + 2 * i + 1]);
    }
    if (idx < 256) g_barz[idx] = bih[idx] + bhh[idx];
    if (idx < 128) { g_bann[idx] = bhh[256 + idx]; g_bain[idx] = bih[256 + idx]; }
}

// ---------------- fused gru1 (PERSISTENT, reg-resident softmax state) --------
// 148 blocks, each loops over seq-tiles (64 seqs). Weights loaded ONCE.
// 2 syncs/step; softmax(M,Z) per owner thread in regs; V-update fused in staging.
__global__ void __launch_bounds__(512) gru1_fused(
    const float* __restrict__ x,
    const float* __restrict__ aw, const float* __restrict__ abp,
    float* __restrict__ out)
{
    extern __shared__ char smraw[];
    uint32_t* Brz = (uint32_t*)smraw;            // 256 x 76
    uint32_t* Bn  = Brz + 256 * BRZS1;           // 128 x 68
    uint32_t* Bxn = Bn + 128 * BNS1;             // 128 x 12
    uint32_t* pA  = Bxn + 128 * BXS1;            // 64 x 76
    float* Vsm  = (float*)(pA + 64 * PAS1);      // 64 x 130 (even base)
    float* scp  = Vsm + 64 * 130;                // 64 x 8
    float* sbrz = scp + 512;                     // 256 (r bias | z bias)
    float* sbn  = sbrz + 256;                    // 128
    float* sbi  = sbn + 128;                     // 128
    float* sba  = sbi + 128;                     // 128

    const int tid = threadIdx.x, lane = tid & 31, warp = tid >> 5;
    const int gid = lane >> 2, tig = lane & 3;
    const int wq = warp & 1, cq = warp >> 1;
    const int mw = wq * 32, jw = cq * 16;
    const int NT = 512;

    // weights + constants loaded ONCE per block
    for (int i = tid; i < 256 * 72; i += NT) Brz[(i / 72) * BRZS1 + (i % 72)] = g_pb1rz[i];
    for (int i = tid; i < 128 * 64; i += NT) Bn[(i / 64) * BNS1 + (i % 64)] = g_pb1n[i];
    for (int i = tid; i < 128 * 12; i += NT) {
        int r = i / BXS1, c = i % BXS1;
        Bxn[i] = (c < 8) ? g_pb1xn[r * 8 + c] : 0u;
    }
    if (tid < 256) sbrz[tid] = g_b1rz[tid];
    if (tid < 128) { sbn[tid] = g_b1nn[tid]; sbi[tid] = g_b1in[tid]; sba[tid] = aw[tid]; }

    const int m_ = lane >> 3, rr = lane & 7;
    const uint32_t aA0  = smem_u32(&pA[(mw + (m_ & 1) * 8 + rr) * PAS1 + (m_ >> 1) * 4]);
    const uint32_t aA1  = aA0 + 16 * PAS1 * 4;
    const uint32_t aBr  = smem_u32(&Brz[(jw + (m_ >> 1) * 8 + rr) * BRZS1 + (m_ & 1) * 4]);
    const uint32_t aBz  = aBr + 128 * BRZS1 * 4;
    const uint32_t aBnn = smem_u32(&Bn[(jw + (m_ >> 1) * 8 + rr) * BNS1 + (m_ & 1) * 4]);
    const uint32_t aBx  = smem_u32(&Bxn[(jw + (m_ >> 1) * 8 + rr) * BXS1 + (m_ & 1) * 4]);

    const float ab = abp[0];
    const int xr = tid >> 3, xc = tid & 7;   // staging coords (one float2/thread)

    for (int tile = blockIdx.x; tile < NSEQ1 / 64; tile += gridDim.x) {
        const int bm = tile * 64;
        float hreg[16];
        #pragma unroll
        for (int i = 0; i < 16; i++) hreg[i] = 0.f;
        float Mreg[2][2], Zreg[2][2];
        #pragma unroll
        for (int mt = 0; mt < 2; mt++)
            #pragma unroll
            for (int half = 0; half < 2; half++) { Mreg[mt][half] = -INFINITY; Zreg[mt][half] = 0.f; }
        float2 xreg = *(const float2*)&x[(size_t)(bm + xr) * 80 + 0 * 16 + xc * 2];

        for (int t = 0; t < DD; t++) {
            __syncthreads();   // sync1: prev epilogue scp + prev MMA pA reads done
            pA[xr * PAS1 + 64 + xc] = packbf(xreg.x, xreg.y);
            if (t > 0) {
                // pack h_{t-1}
                #pragma unroll
                for (int mt = 0; mt < 2; mt++)
                    #pragma unroll
                    for (int half = 0; half < 2; half++) {
                        const int row = mw + mt * 16 + gid + half * 8;
                        #pragma unroll
                        for (int nt = 0; nt < 2; nt++) {
                            const int hix = ((mt * 2 + nt) * 2 + half) * 2;
                            pA[row * PAS1 + cq * 8 + nt * 4 + tig] =
                                packbf(hreg[hix], hreg[hix + 1]);
                        }
                    }
                // online softmax update for step t-1 + V accumulation
                #pragma unroll
                for (int mt = 0; mt < 2; mt++)
                    #pragma unroll
                    for (int half = 0; half < 2; half++) {
                        const int row = mw + mt * 16 + gid + half * 8;
                        float s = ab;
                        #pragma unroll
                        for (int w = 0; w < 8; w++) s += scp[row * 8 + w];
                        const float mo = Mreg[mt][half];
                        const float mn = fmaxf(mo, s);
                        const float c1 = __expf(mo - mn), c2 = __expf(s - mn);
                        Zreg[mt][half] = Zreg[mt][half] * c1 + c2;
                        Mreg[mt][half] = mn;
                        #pragma unroll
                        for (int nt = 0; nt < 2; nt++) {
                            const int jb = jw + nt * 8 + tig * 2;
                            const int hix = ((mt * 2 + nt) * 2 + half) * 2;
                            if (t == 1) {
                                float2 vv;
                                vv.x = hreg[hix] * c2;
                                vv.y = hreg[hix + 1] * c2;
                                *(float2*)&Vsm[row * 130 + jb] = vv;
                            } else {
                                float2 vv = *(float2*)&Vsm[row * 130 + jb];
                                vv.x = vv.x * c1 + hreg[hix] * c2;
                                vv.y = vv.y * c1 + hreg[hix + 1] * c2;
                                *(float2*)&Vsm[row * 130 + jb] = vv;
                            }
                        }
                    }
            }
            __syncthreads();   // sync2: pA staged
            if (t < DD - 1)    // prefetch next x; MMA phase hides the LDG
                xreg = *(const float2*)&x[(size_t)(bm + xr) * 80 + (t + 1) * 16 + xc * 2];

            float accr[2][2][4] = {}, accz[2][2][4] = {};
            float accn[2][2][4] = {}, accg[2][2][4] = {};
            if (t > 0) {
                #pragma unroll
                for (int c = 0; c < 8; c++) {
                    uint32_t af[2][4];
                    ldsm4(af[0], aA0 + c * 32);
                    ldsm4(af[1], aA1 + c * 32);
                    uint32_t brf[4], bzf[4], bnf[4];
                    ldsm4(brf, aBr + c * 32);
                    ldsm4(bzf, aBz + c * 32);
                    ldsm4(bnf, aBnn + c * 32);
                    #pragma unroll
                    for (int mt = 0; mt < 2; mt++) {
                        mma16(accr[mt][0], af[mt], brf[0], brf[1]);
                        mma16(accr[mt][1], af[mt], brf[2], brf[3]);
                        mma16(accz[mt][0], af[mt], bzf[0], bzf[1]);
                        mma16(accz[mt][1], af[mt], bzf[2], bzf[3]);
                        mma16(accn[mt][0], af[mt], bnf[0], bnf[1]);
                        mma16(accn[mt][1], af[mt], bnf[2], bnf[3]);
                    }
                }
            }
            {
                uint32_t af[2][4];
                ldsm4(af[0], aA0 + 8 * 32);
                ldsm4(af[1], aA1 + 8 * 32);
                uint32_t brf[4], bzf[4], bxf[4];
                ldsm4(brf, aBr + 8 * 32);
                ldsm4(bzf, aBz + 8 * 32);
                ldsm4(bxf, aBx);
                #pragma unroll
                for (int mt = 0; mt < 2; mt++) {
                    mma16(accr[mt][0], af[mt], brf[0], brf[1]);
                    mma16(accr[mt][1], af[mt], brf[2], brf[3]);
                    mma16(accz[mt][0], af[mt], bzf[0], bzf[1]);
                    mma16(accz[mt][1], af[mt], bzf[2], bzf[3]);
                    mma16(accg[mt][0], af[mt], bxf[0], bxf[1]);
                    mma16(accg[mt][1], af[mt], bxf[2], bxf[3]);
                }
            }

            // epilogue: gates, h update (regs), attn partials, scp write
            float sc[2][2] = {};
            #pragma unroll
            for (int nt = 0; nt < 2; nt++) {
                const int jb = jw + nt * 8 + tig * 2;
                const float br0 = sbrz[jb], br1 = sbrz[jb + 1];
                const float bz0 = sbrz[128 + jb], bz1 = sbrz[128 + jb + 1];
                const float bn0 = sbn[jb], bn1 = sbn[jb + 1];
                const float bi0 = sbi[jb], bi1 = sbi[jb + 1];
                const float aw0 = sba[jb], aw1 = sba[jb + 1];
                #pragma unroll
                for (int mt = 0; mt < 2; mt++)
                    #pragma unroll
                    for (int half = 0; half < 2; half++) {
                        const int hix = ((mt * 2 + nt) * 2 + half) * 2;
                        {
                            const float r_ = sig_ap(accr[mt][nt][half * 2] + br0);
                            const float z_ = sig_ap(accz[mt][nt][half * 2] + bz0);
                            const float n_ = tanh_ap(accg[mt][nt][half * 2] + bi0
                                           + r_ * (accn[mt][nt][half * 2] + bn0));
                            const float h = (1.f - z_) * n_ + z_ * hreg[hix];
                            hreg[hix] = h;
                            sc[mt][half] += h * aw0;
                        }
                        {
                            const float r_ = sig_ap(accr[mt][nt][half * 2 + 1] + br1);
                            const float z_ = sig_ap(accz[mt][nt][half * 2 + 1] + bz1);
                            const float n_ = tanh_ap(accg[mt][nt][half * 2 + 1] + bi1
                                           + r_ * (accn[mt][nt][half * 2 + 1] + bn1));
                            const float h = (1.f - z_) * n_ + z_ * hreg[hix + 1];
                            hreg[hix + 1] = h;
                            sc[mt][half] += h * aw1;
                        }
                    }
            }
            #pragma unroll
            for (int mt = 0; mt < 2; mt++)
                #pragma unroll
                for (int half = 0; half < 2; half++) {
                    float v = sc[mt][half];
                    v += __shfl_xor_sync(0xffffffffu, v, 1);
                    v += __shfl_xor_sync(0xffffffffu, v, 2);
                    if (tig == 0)
                        scp[(mw + mt * 16 + gid + half * 8) * 8 + cq] = v;
                }
        }
        // tail: fold last step's score + normalize, owner writes out
        __syncthreads();
        #pragma unroll
        for (int mt = 0; mt < 2; mt++)
            #pragma unroll
            for (int half = 0; half < 2; half++) {
                const int row = mw + mt * 16 + gid + half * 8;
                float s = ab;
                #pragma unroll
                for (int w = 0; w < 8; w++) s += scp[row * 8 + w];
                const float mo = Mreg[mt][half];
                const float mn = fmaxf(mo, s);
                const float c1 = __expf(mo - mn), c2 = __expf(s - mn);
                const float Z = Zreg[mt][half] * c1 + c2;
                const float inv = 1.f / Z;
                #pragma unroll
                for (int nt = 0; nt < 2; nt++) {
                    const int jb = jw + nt * 8 + tig * 2;
                    const int hix = ((mt * 2 + nt) * 2 + half) * 2;
                    const float2 vv = *(const float2*)&Vsm[row * 130 + jb];
                    float2 o;
                    o.x = (vv.x * c1 + hreg[hix] * c2) * inv;
                    o.y = (vv.y * c1 + hreg[hix + 1] * c2) * inv;
                    *(float2*)&out[(size_t)(bm + row) * 128 + jb] = o;
                }
            }
    }
}

// ---------------- fused la GRU (32 steps, reg-resident softmax state) --------
// 16 seqs/block, 128 blocks, 16 warps (512 thr). 2 syncs/step.
__global__ void __launch_bounds__(512) la_fused(
    const float* __restrict__ xs,
    const float* __restrict__ aw, const float* __restrict__ abp,
    float* __restrict__ out)
{
    extern __shared__ char smraw[];
    uint32_t* Brz = (uint32_t*)smraw;            // 256 x 132
    uint32_t* Bn  = Brz + 256 * BRZSA;           // 128 x 68
    uint32_t* Bxn = Bn + 128 * BNSA;             // 128 x 68
    uint32_t* pA  = Bxn + 128 * BNSA;            // 16 x 132
    float* Vsm  = (float*)(pA + 16 * PASA);      // 16 x 130 (even base)
    float* scp  = Vsm + 16 * 130;                // 16 x 16
    float* sbn  = scp + 256;                     // 128
    float* sbi  = sbn + 128;                     // 128
    float* sba  = sbi + 128;                     // 128

    const int tid = threadIdx.x, lane = tid & 31, warp = tid >> 5;
    const int gid = lane >> 2, tig = lane & 3;
    const int jw = warp * 8;
    const int bm = blockIdx.x * 16;
    const int NT = 512;

    for (int i = tid; i < 256 * 128; i += NT) Brz[(i / 128) * BRZSA + (i % 128)] = g_pbarz[i];
    for (int i = tid; i < 128 * 64; i += NT) {
        Bn[(i / 64) * BNSA + (i % 64)]  = g_pban[i];
        Bxn[(i / 64) * BNSA + (i % 64)] = g_paxn[i];
    }
    if (tid < 128) { sbn[tid] = g_bann[tid]; sbi[tid] = g_bain[tid]; sba[tid] = aw[tid]; }

    const int m_ = lane >> 3, rr = lane & 7;
    const uint32_t aA  = smem_u32(&pA[((m_ & 1) * 8 + rr) * PASA + (m_ >> 1) * 4]);
    const int lm = lane & 15;
    const int brow = jw + (lm & 7), bcol = ((lm >> 3) & 1) * 4;
    const uint32_t aBr = smem_u32(&Brz[brow * BRZSA + bcol]);
    const uint32_t aBz = aBr + 128 * BRZSA * 4;
    const uint32_t aBnn = smem_u32(&Bn[brow * BNSA + bcol]);
    const uint32_t aBx  = smem_u32(&Bxn[brow * BNSA + bcol]);

    float brj[2], bzj[2];
    #pragma unroll
    for (int e = 0; e < 2; e++) {
        const int j = jw + tig * 2 + e;
        brj[e] = g_barz[j];
        bzj[e] = g_barz[128 + j];
    }
    const float ab = abp[0];

    float hreg[4];
    #pragma unroll
    for (int i = 0; i < 4; i++) hreg[i] = 0.f;
    float Mreg[2], Zreg[2];
    Mreg[0] = Mreg[1] = -INFINITY;
    Zreg[0] = Zreg[1] = 0.f;

    // staging coords: i in {tid, tid+512}
    const int xr0 = tid >> 6, xc0 = tid & 63;
    const int xr1 = (tid + 512) >> 6, xc1 = (tid + 512) & 63;
    float2 xg0 = *(const float2*)&xs[((size_t)(bm + xr0) * WK + 0) * 128 + xc0 * 2];
    float2 xg1 = *(const float2*)&xs[((size_t)(bm + xr1) * WK + 0) * 128 + xc1 * 2];

    for (int t = 0; t < WK; t++) {
        __syncthreads();
        pA[xr0 * PASA + 64 + xc0] = packbf(xg0.x, xg0.y);
        pA[xr1 * PASA + 64 + xc1] = packbf(xg1.x, xg1.y);
        if (t > 0) {
            #pragma unroll
            for (int half = 0; half < 2; half++) {
                const int row = gid + half * 8;
                const int hix = half * 2;
                pA[row * PASA + (jw >> 1) + tig] = packbf(hreg[hix], hreg[hix + 1]);
            }
            // softmax update for step t-1 + V accumulation
            const int jb = jw + tig * 2;
            #pragma unroll
            for (int half = 0; half < 2; half++) {
                const int row = gid + half * 8;
                float s = ab;
                #pragma unroll
                for (int w = 0; w < 16; w++) s += scp[row * 16 + w];
                const float mo = Mreg[half];
                const float mn = fmaxf(mo, s);
                const float c1 = __expf(mo - mn), c2 = __expf(s - mn);
                Zreg[half] = Zreg[half] * c1 + c2;
                Mreg[half] = mn;
                const int hix = half * 2;
                if (t == 1) {
                    float2 vv;
                    vv.x = hreg[hix] * c2;
                    vv.y = hreg[hix + 1] * c2;
                    *(float2*)&Vsm[row * 130 + jb] = vv;
                } else {
                    float2 vv = *(float2*)&Vsm[row * 130 + jb];
                    vv.x = vv.x * c1 + hreg[hix] * c2;
                    vv.y = vv.y * c1 + hreg[hix + 1] * c2;
                    *(float2*)&Vsm[row * 130 + jb] = vv;
                }
            }
        }
        __syncthreads();
        if (t < WK - 1) {
            xg0 = *(const float2*)&xs[((size_t)(bm + xr0) * WK + t + 1) * 128 + xc0 * 2];
            xg1 = *(const float2*)&xs[((size_t)(bm + xr1) * WK + t + 1) * 128 + xc1 * 2];
        }

        float accr[4] = {}, accz[4] = {}, accn[4] = {}, accg[4] = {};
        if (t > 0) {
            #pragma unroll
            for (int c = 0; c < 8; c++) {
                uint32_t af[4];
                ldsm4(af, aA + c * 32);
                uint32_t br[2], bz[2], bn_[2];
                ldsm2(br, aBr + c * 32);
                ldsm2(bz, aBz + c * 32);
                ldsm2(bn_, aBnn + c * 32);
                mma16(accr, af, br[0], br[1]);
                mma16(accz, af, bz[0], bz[1]);
                mma16(accn, af, bn_[0], bn_[1]);
            }
        }
        #pragma unroll
        for (int c = 8; c < 16; c++) {
            uint32_t af[4];
            ldsm4(af, aA + c * 32);
            uint32_t br[2], bz[2], bx[2];
            ldsm2(br, aBr + c * 32);
            ldsm2(bz, aBz + c * 32);
            ldsm2(bx, aBx + (c - 8) * 32);
            mma16(accr, af, br[0], br[1]);
            mma16(accz, af, bz[0], bz[1]);
            mma16(accg, af, bx[0], bx[1]);
        }

        float sc[2] = {0.f, 0.f};
        const int jb = jw + tig * 2;
        const float bn0 = sbn[jb], bn1 = sbn[jb + 1];
        const float bi0 = sbi[jb], bi1 = sbi[jb + 1];
        const float aw0 = sba[jb], aw1 = sba[jb + 1];
        #pragma unroll
        for (int half = 0; half < 2; half++) {
            const int hix = half * 2;
            {
                const float r_ = sig_ap(accr[half * 2] + brj[0]);
                const float z_ = sig_ap(accz[half * 2] + bzj[0]);
                const float n_ = tanh_ap(accg[half * 2] + bi0
                               + r_ * (accn[half * 2] + bn0));
                const float h = (1.f - z_) * n_ + z_ * hreg[hix];
                hreg[hix] = h;
                sc[half] += h * aw0;
            }
            {
                const float r_ = sig_ap(accr[half * 2 + 1] + brj[1]);
                const float z_ = sig_ap(accz[half * 2 + 1] + bzj[1]);
                const float n_ = tanh_ap(accg[half * 2 + 1] + bi1
                               + r_ * (accn[half * 2 + 1] + bn1));
                const float h = (1.f - z_) * n_ + z_ * hreg[hix + 1];
                hreg[hix + 1] = h;
                sc[half] += h * aw1;
            }
        }
        #pragma unroll
        for (int half = 0; half < 2; half++) {
            float v = sc[half];
            v += __shfl_xor_sync(0xffffffffu, v, 1);
            v += __shfl_xor_sync(0xffffffffu, v, 2);
            if (tig == 0) scp[(gid + half * 8) * 16 + warp] = v;
        }
    }
    // tail
    __syncthreads();
    {
        const int jb = jw + tig * 2;
        #pragma unroll
        for (int half = 0; half < 2; half++) {
            const int row = gid + half * 8;
            float s = ab;
            #pragma unroll
            for (int w = 0; w < 16; w++) s += scp[row * 16 + w];
            const float mo = Mreg[half];
            const float mn = fmaxf(mo, s);
            const float c1 = __expf(mo - mn), c2 = __expf(s - mn);
            const float Z = Zreg[half] * c1 + c2;
            const float inv = 1.f / Z;
            const int hix = half * 2;
            const float2 vv = *(const float2*)&Vsm[row * 130 + jb];
            float2 o;
            o.x = (vv.x * c1 + hreg[hix] * c2) * inv;
            o.y = (vv.y * c1 + hreg[hix + 1] * c2) * inv;
            *(float2*)&out[(size_t)(bm + row) * 128 + jb] = o;
        }
    }
}

// ---------------- tf32 GEMM (gig only): C = A @ B^T + bias -------------------
__global__ void __launch_bounds__(256) tgemm(
    const float* __restrict__ A, const float* __restrict__ B,
    const float* __restrict__ bias, float* __restrict__ C,
    int M, int N, int K)
{
    __shared__ float As[64 * 132];
    __shared__ float Bs[128 * 20];
    const int AS = K + 4;
    const int tid = threadIdx.x, lane = tid & 31, warp = tid >> 5;
    const int gid = lane >> 2, tig = lane & 3;
    const int mw = (warp & 1) * 32, jw = (warp >> 1) * 32;
    const int bm = blockIdx.y * 64, bn = blockIdx.x * 128;
    {
        const int arow = tid >> 2, q = tid & 3;
        const float* ap = A + (size_t)(bm + arow) * K;
        const int cpt = K >> 2;
        for (int f = 0; f < (K >> 4); f++) {
            int col = q * cpt + f * 4;
            *(float4*)&As[arow * AS + col] = cvt4(*(const float4*)(ap + col));
        }
    }
    float acc[2][4][4] = {};
    const int NCH = K >> 4;
    for (int c = 0; c < NCH; c++) {
        {
            const int brow = tid >> 1, bq = tid & 1;
            const float* bp = B + (size_t)(bn + brow) * K + c * 16 + bq * 8;
            *(float4*)&Bs[brow * 20 + bq * 8]     = cvt4(*(const float4*)bp);
            *(float4*)&Bs[brow * 20 + bq * 8 + 4] = cvt4(*(const float4*)(bp + 4));
        }
        __syncthreads();
        #pragma unroll
        for (int kk = 0; kk < 2; kk++) {
            const int co = c * 16 + kk * 8 + tig;
            float a[2][4];
            #pragma unroll
            for (int mt = 0; mt < 2; mt++) {
                const int ro = mw + mt * 16 + gid;
                a[mt][0] = As[ro * AS + co];
                a[mt][1] = As[(ro + 8) * AS + co];
                a[mt][2] = As[ro * AS + co + 4];
                a[mt][3] = As[(ro + 8) * AS + co + 4];
            }
            #pragma unroll
            for (int nt = 0; nt < 4; nt++) {
                const int n = jw + nt * 8 + gid;
                float b[2];
                b[0] = Bs[n * 20 + kk * 8 + tig];
                b[1] = Bs[n * 20 + kk * 8 + tig + 4];
                #pragma unroll
                for (int mt = 0; mt < 2; mt++) mma8(acc[mt][nt], a[mt], b);
            }
        }
        __syncthreads();
    }
    #pragma unroll
    for (int nt = 0; nt < 4; nt++) {
        const int col = bn + jw + nt * 8 + tig * 2;
        const float2 bb = *(const float2*)&bias[col];
        #pragma unroll
        for (int mt = 0; mt < 2; mt++)
            #pragma unroll
            for (int half = 0; half < 2; half++) {
                const int row = bm + mw + mt * 16 + gid + half * 8;
                float2 o;
                o.x = acc[mt][nt][half * 2]     + bb.x;
                o.y = acc[mt][nt][half * 2 + 1] + bb.y;
                *(float2*)&C[(size_t)row * N + col] = o;
            }
    }
}

// --------- Wh = last @ gat_intra_W ; s1 = Wh@a1 ; s2 = Wh@a2 ------------------
__global__ void __launch_bounds__(128) wh_intra_kernel(
    const float* __restrict__ W, const float* __restrict__ a)
{
    const int s = blockIdx.x, t = threadIdx.x;
    __shared__ float row[128];
    __shared__ float r1[128], r2[128];
    row[t] = g_short[(size_t)(s * WK + WK - 1) * 128 + t];
    __syncthreads();
    float acc = 0.f;
    #pragma unroll 4
    for (int k = 0; k < 128; k++) acc += row[k] * W[k * 128 + t];
    g_Wh[s * 128 + t] = acc;
    r1[t] = acc * a[t];
    r2[t] = acc * a[128 + t];
    __syncthreads();
    for (int off = 64; off; off >>= 1) {
        if (t < off) { r1[t] += r1[t + off]; r2[t] += r2[t + off]; }
        __syncthreads();
    }
    if (t == 0) { g_s1[s] = r1[0]; g_s2[s] = r2[0]; }
}

// ---------------- sector membership lists ------------------------------------
__global__ void __launch_bounds__(256) build_sectors(const int* __restrict__ sec)
{
    __shared__ int cnt[NSEC];
    const int tid = threadIdx.x;
    if (tid < NSEC) cnt[tid] = 0;
    __syncthreads();
    for (int s = tid; s < S_; s += 256) atomicAdd(&cnt[sec[s]], 1);
    __syncthreads();
    if (tid == 0) {
        int o = 0;
        for (int c = 0; c < NSEC; c++) { g_secoff[c] = o; o += cnt[c]; }
        g_secoff[NSEC] = o;
    }
    if (tid < NSEC) {
        int c = tid, p = 0;
        for (int q = 0; q < c; q++) p += cnt[q];
        for (int s = 0; s < S_; s++)
            if (sec[s] == c) g_secmem[p++] = s;
    }
}

// ---------------- intra GAT via sector lists ----------------------------------
__global__ void __launch_bounds__(128) gat_intra2(const int* __restrict__ sec)
{
    const int i = blockIdx.x, t = threadIdx.x;
    __shared__ int   mem[S_];
    __shared__ float s2m[S_];
    __shared__ float wm[S_];
    __shared__ float rm[128], rz[128];
    const int c = sec[i];
    const int base = g_secoff[c];
    const int n = g_secoff[c + 1] - base;
    for (int j = t; j < n; j += 128) {
        int idx = g_secmem[base + j];
        mem[j] = idx;
        s2m[j] = g_s2[idx];
    }
    __syncthreads();
    const float s1i = g_s1[i];
    float lm = -INFINITY, lz = 0.f;
    for (int j = t; j < n; j += 128) {
        float e = s1i + s2m[j];
        e = e > 0.f ? e : ALPHA * e;
        float mn = fmaxf(lm, e);
        lz = lz * expf(lm - mn) + expf(e - mn);
        lm = mn;
    }
    rm[t] = lm; rz[t] = lz;
    __syncthreads();
    for (int off = 64; off; off >>= 1) {
        if (t < off) {
            float m1 = rm[t], z1 = rz[t], m2 = rm[t + off], z2 = rz[t + off];
            float mn = fmaxf(m1, m2);
            float z = 0.f;
            if (z1 > 0.f) z += z1 * expf(m1 - mn);
            if (z2 > 0.f) z += z2 * expf(m2 - mn);
            rm[t] = mn; rz[t] = z;
        }
        __syncthreads();
    }
    const float Mv = rm[0], Zi = 1.f / rz[0];
    __syncthreads();
    for (int j = t; j < n; j += 128) {
        float e = s1i + s2m[j];
        e = e > 0.f ? e : ALPHA * e;
        wm[j] = expf(e - Mv) * Zi;
    }
    __syncthreads();
    float acc = 0.f;
    for (int j = 0; j < n; j++)
        acc += wm[j] * g_Wh[mem[j] * 128 + t];
    g_intra[i * 128 + t] = acc > 0.f ? acc : expf(acc) - 1.f;
}

// ---------------- lg: single-step GRU with h0=0 (gh = bhh) --------------------
__global__ void __launch_bounds__(256) lg_kernel(const float* __restrict__ bhh)
{
    int idx = blockIdx.x * 256 + threadIdx.x;
    if (idx >= S_ * 128) return;
    int s = idx >> 7, j = idx & 127;
    const float* gp = g_gig + (size_t)s * G3;
    float r = sigf(gp[j] + bhh[j]);
    float z = sigf(gp[128 + j] + bhh[128 + j]);
    float n = tanhf(gp[256 + j] + r * bhh[256 + j]);
    g_lg[idx] = (1.f - z) * n;
}

// ---------------- sector mean of lg ------------------------------------------
__global__ void __launch_bounds__(128) secmean2()
{
    const int c = blockIdx.x, t = threadIdx.x;
    const int base = g_secoff[c];
    const int n = g_secoff[c + 1] - base;
    float sum = 0.f;
    for (int j = 0; j < n; j++)
        sum += g_lg[g_secmem[base + j] * 128 + t];
    g_sec[c * 128 + t] = sum / fmaxf((float)n, 1.f);
}

// ---------------- inter GAT (16x16, exact NEG semantics) ----------------------
__global__ void __launch_bounds__(256) gat_inter_kernel(
    const int* __restrict__ adj, const float* __restrict__ W,
    const float* __restrict__ a)
{
    const int tid = threadIdx.x;
    __shared__ float Whs[NSEC * 128];
    __shared__ float s1g[NSEC], s2g[NSEC];
    __shared__ float att[NSEC * NSEC];
    for (int idx = tid; idx < NSEC * 128; idx += 256) {
        int i = idx >> 7, n = idx & 127;
        float acc = 0.f;
        for (int k = 0; k < 128; k++) acc += g_sec[i * 128 + k] * W[k * 128 + n];
        Whs[idx] = acc;
    }
    __syncthreads();
    if (tid < 32) {
        int i = tid & 15, which = tid >> 4;
        float acc = 0.f;
        for (int n = 0; n < 128; n++) acc += Whs[i * 128 + n] * a[which * 128 + n];
        if (which == 0) s1g[i] = acc; else s2g[i] = acc;
    }
    __syncthreads();
    if (tid < NSEC) {
        int i = tid;
        float e[NSEC];
        float mv = -INFINITY;
        for (int j = 0; j < NSEC; j++) {
            float v = s1g[i] + s2g[j];
            v = v > 0.f ? v : ALPHA * v;
            e[j] = (adj[i * NSEC + j] > 0) ? v : NEGV;
            mv = fmaxf(mv, e[j]);
        }
        float z = 0.f;
        for (int j = 0; j < NSEC; j++) { e[j] = expf(e[j] - mv); z += e[j]; }
        float zi = 1.f / z;
        for (int j = 0; j < NSEC; j++) att[i * NSEC + j] = e[j] * zi;
    }
    __syncthreads();
    for (int idx = tid; idx < NSEC * 128; idx += 256) {
        int i = idx >> 7, n = idx & 127;
        float acc = 0.f;
        #pragma unroll
        for (int j = 0; j < NSEC; j++) acc += att[i * NSEC + j] * Whs[j * 128 + n];
        g_secout[idx] = acc > 0.f ? acc : expf(acc) - 1.f;
    }
}

// ---------------- fusion + heads ---------------------------------------------
__global__ void __launch_bounds__(128) fused_kernel(
    const int* __restrict__ sec,
    const float* __restrict__ fw, const float* __restrict__ fb,
    const float* __restrict__ rw, const float* __restrict__ rb,
    const float* __restrict__ mw, const float* __restrict__ mb,
    float* __restrict__ out)
{
    const int s = blockIdx.x, t = threadIdx.x;
    __shared__ float cat[G3];
    __shared__ float r1[128], r2[128];
    cat[t]       = g_lg[s * 128 + t];
    cat[128 + t] = g_la[s * 128 + t];
    cat[256 + t] = g_secout[sec[s] * 128 + t];
    __syncthreads();
    float f = fb[t];
    #pragma unroll 4
    for (int k = 0; k < G3; k++) f += cat[k] * fw[k * 128 + t];
    r1[t] = f * rw[t];
    r2[t] = f * mw[t];
    __syncthreads();
    for (int off = 64; off; off >>= 1) {
        if (t < off) { r1[t] += r1[t + off]; r2[t] += r2[t + off]; }
        __syncthreads();
    }
    if (t == 0) {
        out[s]      = r1[0] + rb[0];
        out[S_ + s] = sigf(r2[0] + mb[0]);
    }
}

// ---------------- launch -----------------------------------------------------
extern "C" void kernel_launch(void* const* d_in, const int* in_sizes, int n_in,
                              void* d_out, int out_size)
{
    const float* x     = (const float*)d_in[0];
    const int*   sec   = (const int*)  d_in[1];
    const int*   adj   = (const int*)  d_in[2];
    const float* g1Wih = (const float*)d_in[3];
    const float* g1Whh = (const float*)d_in[4];
    const float* g1bih = (const float*)d_in[5];
    const float* g1bhh = (const float*)d_in[6];
    const float* a1w   = (const float*)d_in[7];
    const float* a1b   = (const float*)d_in[8];
    const float* giW   = (const float*)d_in[9];
    const float* gintra_a = (const float*)d_in[10];
    const float* ggWih = (const float*)d_in[11];
    const float* ggbih = (const float*)d_in[13];
    const float* ggbhh = (const float*)d_in[14];
    const float* gaWih = (const float*)d_in[17];
    const float* gaWhh = (const float*)d_in[18];
    const float* gabih = (const float*)d_in[19];
    const float* gabhh = (const float*)d_in[20];
    const float* aaw   = (const float*)d_in[21];
    const float* aab   = (const float*)d_in[22];
    const float* gintW = (const float*)d_in[23];
    const float* ginter_a = (const float*)d_in[24];
    const float* fw    = (const float*)d_in[25];
    const float* fb    = (const float*)d_in[26];
    const float* rw    = (const float*)d_in[27];
    const float* rb    = (const float*)d_in[28];
    const float* mw    = (const float*)d_in[29];
    const float* mb    = (const float*)d_in[30];
    float* out = (float*)d_out;

    float *p_short, *p_intra, *p_gig, *p_la;
    cudaGetSymbolAddress((void**)&p_short, g_short);
    cudaGetSymbolAddress((void**)&p_intra, g_intra);
    cudaGetSymbolAddress((void**)&p_gig,   g_gig);
    cudaGetSymbolAddress((void**)&p_la,    g_la);

    // gru1: 44032 u32 words = 176128 B ; la: 56288 words = 225152 B
    const int sm1 = 176128;
    const int sm2 = 225152;
    cudaFuncSetAttribute(gru1_fused, cudaFuncAttributeMaxDynamicSharedMemorySize, sm1);
    cudaFuncSetAttribute(la_fused,   cudaFuncAttributeMaxDynamicSharedMemorySize, sm2);

    cudaStream_t s2;
    cudaStreamCreateWithFlags(&s2, cudaStreamNonBlocking);
    cudaEvent_t e1, e2;
    cudaEventCreateWithFlags(&e1, cudaEventDisableTiming);
    cudaEventCreateWithFlags(&e2, cudaEventDisableTiming);

    build_sectors<<<1, 256>>>(sec);
    prep1<<<72, 256>>>(g1Whh, g1Wih, g1bih, g1bhh);
    prepa<<<128, 256, 0, s2>>>(gaWhh, gaWih, gabih, gabhh);  // overlaps gru1

    gru1_fused<<<148, 512, sm1>>>(x, a1w, a1b, p_short);      // persistent

    cudaEventRecord(e1, 0);
    cudaStreamWaitEvent(s2, e1, 0);
    la_fused<<<S_ / 16, 512, sm2, s2>>>(p_short, aaw, aab, p_la);

    wh_intra_kernel<<<S_, 128>>>(giW, gintra_a);
    gat_intra2<<<S_, 128>>>(sec);
    tgemm<<<dim3(G3 / 128, S_ / 64), 256>>>(p_intra, ggWih, ggbih, p_gig, S_, G3, EE);
    lg_kernel<<<(S_ * 128 + 255) / 256, 256>>>(ggbhh);
    secmean2<<<NSEC, 128>>>();
    gat_inter_kernel<<<1, 256>>>(adj, gintW, ginter_a);

    cudaEventRecord(e2, s2);
    cudaStreamWaitEvent(0, e2, 0);
    fused_kernel<<<S_, 128>>>(sec, fw, fb, rw, rb, mw, mb, out);

    (void)in_sizes; (void)n_in; (void)out_size;
}

// round 17
// speedup vs baseline: 1.0673x; 1.0673x over previous
#include <cuda_runtime.h>
#include <cuda_bf16.h>
#include <math.h>
#include <stdint.h>

#define ALPHA 0.2f
#define NEGV  -9000000000000000.0f

#define S_    2048
#define WK    32
#define DD    5
#define FF    16
#define HH    128
#define EE    128
#define NSEC  16
#define NSEQ1 (S_*WK)      /* 65536 */
#define G3    384

// ---------------- scratch (device globals; no allocation) ----------------
__device__ float g_short[NSEQ1 * HH];
__device__ float g_Wh[S_ * EE];
__device__ float g_s1[S_];
__device__ float g_s2[S_];
__device__ float g_intra[S_ * EE];
__device__ float g_gig[S_ * G3];
__device__ float g_lg[S_ * EE];
__device__ float g_la[S_ * EE];
__device__ float g_sec[NSEC * EE];
__device__ float g_secout[NSEC * EE];
__device__ int   g_secmem[S_];
__device__ int   g_secoff[NSEC + 1];

// packed bf16 weights (u32 = 2 bf16 along k)
__device__ uint32_t g_pb1rz[256 * 72];   // gru1 [Whh|Wih] for r,z  (k=144)
__device__ uint32_t g_pb1n [128 * 64];   // gru1 Whh_n (k=128)
__device__ uint32_t g_pb1xn[128 * 8];    // gru1 Wih_n (k=16)
__device__ float    g_b1rz[256], g_b1nn[128], g_b1in[128];

__device__ uint32_t g_pbarz[256 * 128];  // la [Whh|Wih] for r,z (k=256)
__device__ uint32_t g_pban [128 * 64];   // la Whh_n (k=128)
__device__ uint32_t g_paxn [128 * 64];   // la Wih_n (k=128)
__device__ float    g_barz[256], g_bann[128], g_bain[128];

__device__ __forceinline__ float sigf(float x) { return 1.f / (1.f + expf(-x)); }
__device__ __forceinline__ float tanh_ap(float x) {
    float y; asm("tanh.approx.f32 %0, %1;" : "=f"(y) : "f"(x)); return y;
}
__device__ __forceinline__ float sig_ap(float x) {
    return 0.5f * tanh_ap(0.5f * x) + 0.5f;
}
__device__ __forceinline__ uint32_t packbf(float a, float b) {
    __nv_bfloat162 t = __floats2bfloat162_rn(a, b);
    return *reinterpret_cast<uint32_t*>(&t);
}
__device__ __forceinline__ float tf32r(float x) {
    uint32_t u;
    asm("cvt.rna.tf32.f32 %0, %1;" : "=r"(u) : "f"(x));
    return __uint_as_float(u);
}
__device__ __forceinline__ void mma8(float* d, const float* a, const float* b) {
    asm volatile(
        "mma.sync.aligned.m16n8k8.row.col.f32.tf32.tf32.f32 "
        "{%0,%1,%2,%3}, {%4,%5,%6,%7}, {%8,%9}, {%0,%1,%2,%3};\n"
        : "+f"(d[0]), "+f"(d[1]), "+f"(d[2]), "+f"(d[3])
        : "r"(__float_as_uint(a[0])), "r"(__float_as_uint(a[1])),
          "r"(__float_as_uint(a[2])), "r"(__float_as_uint(a[3])),
          "r"(__float_as_uint(b[0])), "r"(__float_as_uint(b[1])));
}
__device__ __forceinline__ void mma16(float* d, const uint32_t* a,
                                      uint32_t b0, uint32_t b1) {
    asm volatile(
        "mma.sync.aligned.m16n8k16.row.col.f32.bf16.bf16.f32 "
        "{%0,%1,%2,%3}, {%4,%5,%6,%7}, {%8,%9}, {%0,%1,%2,%3};\n"
        : "+f"(d[0]), "+f"(d[1]), "+f"(d[2]), "+f"(d[3])
        : "r"(a[0]), "r"(a[1]), "r"(a[2]), "r"(a[3]), "r"(b0), "r"(b1));
}
__device__ __forceinline__ float4 cvt4(float4 v) {
    v.x = tf32r(v.x); v.y = tf32r(v.y); v.z = tf32r(v.z); v.w = tf32r(v.w);
    return v;
}
__device__ __forceinline__ uint32_t smem_u32(const void* p) {
    return (uint32_t)__cvta_generic_to_shared(p);
}
__device__ __forceinline__ void ldsm4(uint32_t* r, uint32_t addr) {
    asm volatile("ldmatrix.sync.aligned.m8n8.x4.shared.b16 {%0,%1,%2,%3}, [%4];"
        : "=r"(r[0]), "=r"(r[1]), "=r"(r[2]), "=r"(r[3]) : "r"(addr));
}
__device__ __forceinline__ void ldsm2(uint32_t* r, uint32_t addr) {
    asm volatile("ldmatrix.sync.aligned.m8n8.x2.shared.b16 {%0,%1}, [%2];"
        : "=r"(r[0]), "=r"(r[1]) : "r"(addr));
}

// smem strides (u32 words) — multiples of 4 (16B ldmatrix alignment),
// mod 32 in {4,12} => conflict-free 8-row LDSM phases.
#define BRZS1 76
#define BNS1  68
#define BXS1  12
#define PAS1  76
#define BRZSA 132
#define BNSA  68
#define PASA  132

// ---------------- weight prep ------------------------------------------------
__global__ void __launch_bounds__(256) prep1(
    const float* __restrict__ Whh, const float* __restrict__ Wih,
    const float* __restrict__ bih, const float* __restrict__ bhh)
{
    int idx = blockIdx.x * 256 + threadIdx.x;
    if (idx < 256 * 72) {
        int n = idx / 72, i = idx % 72, k = 2 * i;
        float a, b;
        if (k < 128) { a = Whh[n * 128 + k]; b = Whh[n * 128 + k + 1]; }
        else         { a = Wih[n * 16 + k - 128]; b = Wih[n * 16 + k - 127]; }
        g_pb1rz[idx] = packbf(a, b);
    }
    if (idx < 128 * 64) {
        int j = idx / 64, i = idx % 64;
        g_pb1n[idx] = packbf(Whh[(256 + j) * 128 + 2 * i],
                             Whh[(256 + j) * 128 + 2 * i + 1]);
    }
    if (idx < 128 * 8) {
        int j = idx / 8, i = idx % 8;
        g_pb1xn[idx] = packbf(Wih[(256 + j) * 16 + 2 * i],
                              Wih[(256 + j) * 16 + 2 * i + 1]);
    }
    if (idx < 256) g_b1rz[idx] = bih[idx] + bhh[idx];
    if (idx < 128) { g_b1nn[idx] = bhh[256 + idx]; g_b1in[idx] = bih[256 + idx]; }
}

__global__ void __launch_bounds__(256) prepa(
    const float* __restrict__ Whh, const float* __restrict__ Wih,
    const float* __restrict__ bih, const float* __restrict__ bhh)
{
    int idx = blockIdx.x * 256 + threadIdx.x;
    if (idx < 256 * 128) {
        int n = idx / 128, i = idx % 128, k = 2 * i;
        float a, b;
        if (k < 128) { a = Whh[n * 128 + k]; b = Whh[n * 128 + k + 1]; }
        else         { a = Wih[n * 128 + k - 128]; b = Wih[n * 128 + k - 127]; }
        g_pbarz[idx] = packbf(a, b);
    }
    if (idx < 128 * 64) {
        int j = idx / 64, i = idx % 64;
        g_pban[idx] = packbf(Whh[(256 + j) * 128 + 2 * i],
                             Whh[(256 + j) * 128 + 2 * i + 1]);
        g_paxn[idx] = packbf(Wih[(256 + j) * 128 + 2 * i],
                             Wih[(256 + j) * 128 + 2 * i + 1]);
    }
    if (idx < 256) g_barz[idx] = bih[idx] + bhh[idx];
    if (idx < 128) { g_bann[idx] = bhh[256 + idx]; g_bain[idx] = bih[256 + idx]; }
}

// ---------------- fused gru1 (PERSISTENT, 5 steps/tile, online attn) ---------
// R15 structure (3-sync ladder). t==1 V plain-store (no Vsm init loop).
__global__ void __launch_bounds__(512) gru1_fused(
    const float* __restrict__ x,
    const float* __restrict__ aw, const float* __restrict__ abp,
    float* __restrict__ out)
{
    extern __shared__ char smraw[];
    uint32_t* Brz = (uint32_t*)smraw;            // 256 x 76
    uint32_t* Bn  = Brz + 256 * BRZS1;           // 128 x 68
    uint32_t* Bxn = Bn + 128 * BNS1;             // 128 x 12
    uint32_t* pA  = Bxn + 128 * BXS1;            // 64 x 76
    float* Vsm  = (float*)(pA + 64 * PAS1);      // 64 x 130 (even base)
    float* scp  = Vsm + 64 * 130;                // 64 x 8
    float* Mrow = scp + 512;                     // 64
    float* Zrow = Mrow + 64;
    float* C1   = Zrow + 64;
    float* C2   = C1 + 64;
    float* sbn  = C2 + 64;                       // 128
    float* sbi  = sbn + 128;                     // 128
    float* sba  = sbi + 128;                     // 128

    const int tid = threadIdx.x, lane = tid & 31, warp = tid >> 5;
    const int gid = lane >> 2, tig = lane & 3;
    const int wq = warp & 1, cq = warp >> 1;
    const int mw = wq * 32, jw = cq * 16;
    const int NT = 512;

    // weights + constants loaded ONCE per block
    for (int i = tid; i < 256 * 72; i += NT) Brz[(i / 72) * BRZS1 + (i % 72)] = g_pb1rz[i];
    for (int i = tid; i < 128 * 64; i += NT) Bn[(i / 64) * BNS1 + (i % 64)] = g_pb1n[i];
    for (int i = tid; i < 128 * 12; i += NT) {
        int r = i / BXS1, c = i % BXS1;
        Bxn[i] = (c < 8) ? g_pb1xn[r * 8 + c] : 0u;
    }
    if (tid < 128) { sbn[tid] = g_b1nn[tid]; sbi[tid] = g_b1in[tid]; sba[tid] = aw[tid]; }

    const int m_ = lane >> 3, rr = lane & 7;
    const uint32_t aA0  = smem_u32(&pA[(mw + (m_ & 1) * 8 + rr) * PAS1 + (m_ >> 1) * 4]);
    const uint32_t aA1  = aA0 + 16 * PAS1 * 4;
    const uint32_t aBr  = smem_u32(&Brz[(jw + (m_ >> 1) * 8 + rr) * BRZS1 + (m_ & 1) * 4]);
    const uint32_t aBz  = aBr + 128 * BRZS1 * 4;
    const uint32_t aBnn = smem_u32(&Bn[(jw + (m_ >> 1) * 8 + rr) * BNS1 + (m_ & 1) * 4]);
    const uint32_t aBx  = smem_u32(&Bxn[(jw + (m_ >> 1) * 8 + rr) * BXS1 + (m_ & 1) * 4]);

    float brj[4], bzj[4];
    #pragma unroll
    for (int q = 0; q < 4; q++) {
        const int j = jw + (q >> 1) * 8 + tig * 2 + (q & 1);
        brj[q] = g_b1rz[j];
        bzj[q] = g_b1rz[128 + j];
    }
    const float ab = abp[0];
    const int xr = tid >> 3, xc = tid & 7;   // staging coords (one float2/thread)

    for (int tile = blockIdx.x; tile < NSEQ1 / 64; tile += gridDim.x) {
        const int bm = tile * 64;
        __syncthreads();   // prior tile's output reads done before reinit
        if (tid < 64) { Mrow[tid] = -INFINITY; Zrow[tid] = 0.f; }
        float hreg[16];
        #pragma unroll
        for (int i = 0; i < 16; i++) hreg[i] = 0.f;
        // prefetch x(t=0)
        float2 xreg = *(const float2*)&x[(size_t)(bm + xr) * 80 + 0 * 16 + xc * 2];

        for (int t = 0; t < DD; t++) {
            __syncthreads();
            pA[xr * PAS1 + 64 + xc] = packbf(xreg.x, xreg.y);
            if (t > 0) {
                #pragma unroll
                for (int mt = 0; mt < 2; mt++)
                    #pragma unroll
                    for (int half = 0; half < 2; half++) {
                        const int row = mw + mt * 16 + gid + half * 8;
                        #pragma unroll
                        for (int nt = 0; nt < 2; nt++) {
                            const int hix = ((mt * 2 + nt) * 2 + half) * 2;
                            pA[row * PAS1 + cq * 8 + nt * 4 + tig] =
                                packbf(hreg[hix], hreg[hix + 1]);
                        }
                    }
            }
            __syncthreads();
            if (t < DD - 1)   // prefetch next x; MMA phase hides the LDG
                xreg = *(const float2*)&x[(size_t)(bm + xr) * 80 + (t + 1) * 16 + xc * 2];

            float accr[2][2][4] = {}, accz[2][2][4] = {};
            float accn[2][2][4] = {}, accg[2][2][4] = {};
            if (t > 0) {
                #pragma unroll
                for (int c = 0; c < 8; c++) {
                    uint32_t af[2][4];
                    ldsm4(af[0], aA0 + c * 32);
                    ldsm4(af[1], aA1 + c * 32);
                    uint32_t brf[4], bzf[4], bnf[4];
                    ldsm4(brf, aBr + c * 32);
                    ldsm4(bzf, aBz + c * 32);
                    ldsm4(bnf, aBnn + c * 32);
                    #pragma unroll
                    for (int mt = 0; mt < 2; mt++) {
                        mma16(accr[mt][0], af[mt], brf[0], brf[1]);
                        mma16(accr[mt][1], af[mt], brf[2], brf[3]);
                        mma16(accz[mt][0], af[mt], bzf[0], bzf[1]);
                        mma16(accz[mt][1], af[mt], bzf[2], bzf[3]);
                        mma16(accn[mt][0], af[mt], bnf[0], bnf[1]);
                        mma16(accn[mt][1], af[mt], bnf[2], bnf[3]);
                    }
                }
            }
            {
                uint32_t af[2][4];
                ldsm4(af[0], aA0 + 8 * 32);
                ldsm4(af[1], aA1 + 8 * 32);
                uint32_t brf[4], bzf[4], bxf[4];
                ldsm4(brf, aBr + 8 * 32);
                ldsm4(bzf, aBz + 8 * 32);
                ldsm4(bxf, aBx);
                #pragma unroll
                for (int mt = 0; mt < 2; mt++) {
                    mma16(accr[mt][0], af[mt], brf[0], brf[1]);
                    mma16(accr[mt][1], af[mt], brf[2], brf[3]);
                    mma16(accz[mt][0], af[mt], bzf[0], bzf[1]);
                    mma16(accz[mt][1], af[mt], bzf[2], bzf[3]);
                    mma16(accg[mt][0], af[mt], bxf[0], bxf[1]);
                    mma16(accg[mt][1], af[mt], bxf[2], bxf[3]);
                }
            }

            float sc[2][2] = {};
            #pragma unroll
            for (int nt = 0; nt < 2; nt++) {
                const int jb = jw + nt * 8 + tig * 2;
                const float bn0 = sbn[jb], bn1 = sbn[jb + 1];
                const float bi0 = sbi[jb], bi1 = sbi[jb + 1];
                const float aw0 = sba[jb], aw1 = sba[jb + 1];
                #pragma unroll
                for (int mt = 0; mt < 2; mt++)
                    #pragma unroll
                    for (int half = 0; half < 2; half++) {
                        const int row = mw + mt * 16 + gid + half * 8;
                        const int hix = ((mt * 2 + nt) * 2 + half) * 2;
                        if (t == 1) {
                            const float c2 = C2[row];
                            float2 vv;
                            vv.x = hreg[hix] * c2;
                            vv.y = hreg[hix + 1] * c2;
                            *(float2*)&Vsm[row * 130 + jb] = vv;
                        } else if (t > 1) {
                            const float c1 = C1[row], c2 = C2[row];
                            float2 vv = *(float2*)&Vsm[row * 130 + jb];
                            vv.x = vv.x * c1 + hreg[hix] * c2;
                            vv.y = vv.y * c1 + hreg[hix + 1] * c2;
                            *(float2*)&Vsm[row * 130 + jb] = vv;
                        }
                        {
                            const float r_ = sig_ap(accr[mt][nt][half * 2] + brj[nt * 2]);
                            const float z_ = sig_ap(accz[mt][nt][half * 2] + bzj[nt * 2]);
                            const float n_ = tanh_ap(accg[mt][nt][half * 2] + bi0
                                           + r_ * (accn[mt][nt][half * 2] + bn0));
                            const float h = (1.f - z_) * n_ + z_ * hreg[hix];
                            hreg[hix] = h;
                            sc[mt][half] += h * aw0;
                        }
                        {
                            const float r_ = sig_ap(accr[mt][nt][half * 2 + 1] + brj[nt * 2 + 1]);
                            const float z_ = sig_ap(accz[mt][nt][half * 2 + 1] + bzj[nt * 2 + 1]);
                            const float n_ = tanh_ap(accg[mt][nt][half * 2 + 1] + bi1
                                           + r_ * (accn[mt][nt][half * 2 + 1] + bn1));
                            const float h = (1.f - z_) * n_ + z_ * hreg[hix + 1];
                            hreg[hix + 1] = h;
                            sc[mt][half] += h * aw1;
                        }
                    }
            }
            #pragma unroll
            for (int mt = 0; mt < 2; mt++)
                #pragma unroll
                for (int half = 0; half < 2; half++) {
                    float v = sc[mt][half];
                    v += __shfl_xor_sync(0xffffffffu, v, 1);
                    v += __shfl_xor_sync(0xffffffffu, v, 2);
                    if (tig == 0)
                        scp[(mw + mt * 16 + gid + half * 8) * 8 + cq] = v;
                }
            __syncthreads();
            if (tid < 64) {
                float s = ab;
                #pragma unroll
                for (int w = 0; w < 8; w++) s += scp[tid * 8 + w];
                const float mo = Mrow[tid];
                const float mn = fmaxf(mo, s);
                const float c1 = __expf(mo - mn), c2 = __expf(s - mn);
                Zrow[tid] = Zrow[tid] * c1 + c2;
                Mrow[tid] = mn;
                C1[tid] = c1; C2[tid] = c2;
            }
        }
        __syncthreads();
        #pragma unroll
        for (int nt = 0; nt < 2; nt++) {
            const int jb = jw + nt * 8 + tig * 2;
            #pragma unroll
            for (int mt = 0; mt < 2; mt++)
                #pragma unroll
                for (int half = 0; half < 2; half++) {
                    const int row = mw + mt * 16 + gid + half * 8;
                    const float c1 = C1[row], c2 = C2[row];
                    const float inv = 1.f / Zrow[row];
                    const int hix = ((mt * 2 + nt) * 2 + half) * 2;
                    const float2 vv = *(const float2*)&Vsm[row * 130 + jb];
                    float2 o;
                    o.x = (vv.x * c1 + hreg[hix] * c2) * inv;
                    o.y = (vv.y * c1 + hreg[hix + 1] * c2) * inv;
                    *(float2*)&out[(size_t)(bm + row) * 128 + jb] = o;
                }
        }
    }
}

// ---------------- fused la GRU (32 steps, weights resident) ------------------
// R15 structure; t==1 V plain-store (no Vsm init loop).
__global__ void __launch_bounds__(512) la_fused(
    const float* __restrict__ xs,
    const float* __restrict__ aw, const float* __restrict__ abp,
    float* __restrict__ out)
{
    extern __shared__ char smraw[];
    uint32_t* Brz = (uint32_t*)smraw;            // 256 x 132
    uint32_t* Bn  = Brz + 256 * BRZSA;           // 128 x 68
    uint32_t* Bxn = Bn + 128 * BNSA;             // 128 x 68
    uint32_t* pA  = Bxn + 128 * BNSA;            // 16 x 132
    float* Vsm  = (float*)(pA + 16 * PASA);      // 16 x 130 (even base)
    float* scp  = Vsm + 16 * 130;                // 16 x 16
    float* Mrow = scp + 256;                     // 16
    float* Zrow = Mrow + 16;
    float* C1   = Zrow + 16;
    float* C2   = C1 + 16;
    float* sbn  = C2 + 16;                       // 128
    float* sbi  = sbn + 128;                     // 128
    float* sba  = sbi + 128;                     // 128

    const int tid = threadIdx.x, lane = tid & 31, warp = tid >> 5;
    const int gid = lane >> 2, tig = lane & 3;
    const int jw = warp * 8;
    const int bm = blockIdx.x * 16;
    const int NT = 512;

    for (int i = tid; i < 256 * 128; i += NT) Brz[(i / 128) * BRZSA + (i % 128)] = g_pbarz[i];
    for (int i = tid; i < 128 * 64; i += NT) {
        Bn[(i / 64) * BNSA + (i % 64)]  = g_pban[i];
        Bxn[(i / 64) * BNSA + (i % 64)] = g_paxn[i];
    }
    for (int i = tid; i < 16 * PASA; i += NT) pA[i] = 0u;
    if (tid < 16) { Mrow[tid] = -INFINITY; Zrow[tid] = 0.f; }
    if (tid < 128) { sbn[tid] = g_bann[tid]; sbi[tid] = g_bain[tid]; sba[tid] = aw[tid]; }

    const int m_ = lane >> 3, rr = lane & 7;
    const uint32_t aA  = smem_u32(&pA[((m_ & 1) * 8 + rr) * PASA + (m_ >> 1) * 4]);
    const int lm = lane & 15;
    const int brow = jw + (lm & 7), bcol = ((lm >> 3) & 1) * 4;
    const uint32_t aBr = smem_u32(&Brz[brow * BRZSA + bcol]);
    const uint32_t aBz = aBr + 128 * BRZSA * 4;
    const uint32_t aBnn = smem_u32(&Bn[brow * BNSA + bcol]);
    const uint32_t aBx  = smem_u32(&Bxn[brow * BNSA + bcol]);

    float brj[2], bzj[2];
    #pragma unroll
    for (int e = 0; e < 2; e++) {
        const int j = jw + tig * 2 + e;
        brj[e] = g_barz[j];
        bzj[e] = g_barz[128 + j];
    }
    const float ab = abp[0];

    float hreg[4];
    #pragma unroll
    for (int i = 0; i < 4; i++) hreg[i] = 0.f;

    // staging coords: i in {tid, tid+512}
    const int xr0 = tid >> 6, xc0 = tid & 63;
    const int xr1 = (tid + 512) >> 6, xc1 = (tid + 512) & 63;
    float2 xg0 = *(const float2*)&xs[((size_t)(bm + xr0) * WK + 0) * 128 + xc0 * 2];
    float2 xg1 = *(const float2*)&xs[((size_t)(bm + xr1) * WK + 0) * 128 + xc1 * 2];

    for (int t = 0; t < WK; t++) {
        __syncthreads();
        pA[xr0 * PASA + 64 + xc0] = packbf(xg0.x, xg0.y);
        pA[xr1 * PASA + 64 + xc1] = packbf(xg1.x, xg1.y);
        if (t > 0) {
            #pragma unroll
            for (int half = 0; half < 2; half++) {
                const int row = gid + half * 8;
                const int hix = half * 2;
                pA[row * PASA + (jw >> 1) + tig] = packbf(hreg[hix], hreg[hix + 1]);
            }
        }
        __syncthreads();
        if (t < WK - 1) {
            xg0 = *(const float2*)&xs[((size_t)(bm + xr0) * WK + t + 1) * 128 + xc0 * 2];
            xg1 = *(const float2*)&xs[((size_t)(bm + xr1) * WK + t + 1) * 128 + xc1 * 2];
        }

        float accr[4] = {}, accz[4] = {}, accn[4] = {}, accg[4] = {};
        if (t > 0) {
            #pragma unroll
            for (int c = 0; c < 8; c++) {
                uint32_t af[4];
                ldsm4(af, aA + c * 32);
                uint32_t br[2], bz[2], bn_[2];
                ldsm2(br, aBr + c * 32);
                ldsm2(bz, aBz + c * 32);
                ldsm2(bn_, aBnn + c * 32);
                mma16(accr, af, br[0], br[1]);
                mma16(accz, af, bz[0], bz[1]);
                mma16(accn, af, bn_[0], bn_[1]);
            }
        }
        #pragma unroll
        for (int c = 8; c < 16; c++) {
            uint32_t af[4];
            ldsm4(af, aA + c * 32);
            uint32_t br[2], bz[2], bx[2];
            ldsm2(br, aBr + c * 32);
            ldsm2(bz, aBz + c * 32);
            ldsm2(bx, aBx + (c - 8) * 32);
            mma16(accr, af, br[0], br[1]);
            mma16(accz, af, bz[0], bz[1]);
            mma16(accg, af, bx[0], bx[1]);
        }

        float sc[2] = {0.f, 0.f};
        const int jb = jw + tig * 2;
        const float bn0 = sbn[jb], bn1 = sbn[jb + 1];
        const float bi0 = sbi[jb], bi1 = sbi[jb + 1];
        const float aw0 = sba[jb], aw1 = sba[jb + 1];
        #pragma unroll
        for (int half = 0; half < 2; half++) {
            const int row = gid + half * 8;
            const int hix = half * 2;
            if (t == 1) {
                const float c2 = C2[row];
                float2 vv;
                vv.x = hreg[hix] * c2;
                vv.y = hreg[hix + 1] * c2;
                *(float2*)&Vsm[row * 130 + jb] = vv;
            } else if (t > 1) {
                const float c1 = C1[row], c2 = C2[row];
                float2 vv = *(float2*)&Vsm[row * 130 + jb];
                vv.x = vv.x * c1 + hreg[hix] * c2;
                vv.y = vv.y * c1 + hreg[hix + 1] * c2;
                *(float2*)&Vsm[row * 130 + jb] = vv;
            }
            {
                const float r_ = sig_ap(accr[half * 2] + brj[0]);
                const float z_ = sig_ap(accz[half * 2] + bzj[0]);
                const float n_ = tanh_ap(accg[half * 2] + bi0
                               + r_ * (accn[half * 2] + bn0));
                const float h = (1.f - z_) * n_ + z_ * hreg[hix];
                hreg[hix] = h;
                sc[half] += h * aw0;
            }
            {
                const float r_ = sig_ap(accr[half * 2 + 1] + brj[1]);
                const float z_ = sig_ap(accz[half * 2 + 1] + bzj[1]);
                const float n_ = tanh_ap(accg[half * 2 + 1] + bi1
                               + r_ * (accn[half * 2 + 1] + bn1));
                const float h = (1.f - z_) * n_ + z_ * hreg[hix + 1];
                hreg[hix + 1] = h;
                sc[half] += h * aw1;
            }
        }
        #pragma unroll
        for (int half = 0; half < 2; half++) {
            float v = sc[half];
            v += __shfl_xor_sync(0xffffffffu, v, 1);
            v += __shfl_xor_sync(0xffffffffu, v, 2);
            if (tig == 0) scp[(gid + half * 8) * 16 + warp] = v;
        }
        __syncthreads();
        if (tid < 16) {
            float s = ab;
            #pragma unroll
            for (int w = 0; w < 16; w++) s += scp[tid * 16 + w];
            const float mo = Mrow[tid];
            const float mn = fmaxf(mo, s);
            const float c1 = __expf(mo - mn), c2 = __expf(s - mn);
            Zrow[tid] = Zrow[tid] * c1 + c2;
            Mrow[tid] = mn;
            C1[tid] = c1; C2[tid] = c2;
        }
    }
    __syncthreads();
    {
        const int jb = jw + tig * 2;
        #pragma unroll
        for (int half = 0; half < 2; half++) {
            const int row = gid + half * 8;
            const float c1 = C1[row], c2 = C2[row];
            const float inv = 1.f / Zrow[row];
            const int hix = half * 2;
            const float2 vv = *(const float2*)&Vsm[row * 130 + jb];
            float2 o;
            o.x = (vv.x * c1 + hreg[hix] * c2) * inv;
            o.y = (vv.y * c1 + hreg[hix + 1] * c2) * inv;
            *(float2*)&out[(size_t)(bm + row) * 128 + jb] = o;
        }
    }
}

// ---------------- tf32 GEMM (gig only): C = A @ B^T + bias -------------------
__global__ void __launch_bounds__(256) tgemm(
    const float* __restrict__ A, const float* __restrict__ B,
    const float* __restrict__ bias, float* __restrict__ C,
    int M, int N, int K)
{
    __shared__ float As[64 * 132];
    __shared__ float Bs[128 * 20];
    const int AS = K + 4;
    const int tid = threadIdx.x, lane = tid & 31, warp = tid >> 5;
    const int gid = lane >> 2, tig = lane & 3;
    const int mw = (warp & 1) * 32, jw = (warp >> 1) * 32;
    const int bm = blockIdx.y * 64, bn = blockIdx.x * 128;
    {
        const int arow = tid >> 2, q = tid & 3;
        const float* ap = A + (size_t)(bm + arow) * K;
        const int cpt = K >> 2;
        for (int f = 0; f < (K >> 4); f++) {
            int col = q * cpt + f * 4;
            *(float4*)&As[arow * AS + col] = cvt4(*(const float4*)(ap + col));
        }
    }
    float acc[2][4][4] = {};
    const int NCH = K >> 4;
    for (int c = 0; c < NCH; c++) {
        {
            const int brow = tid >> 1, bq = tid & 1;
            const float* bp = B + (size_t)(bn + brow) * K + c * 16 + bq * 8;
            *(float4*)&Bs[brow * 20 + bq * 8]     = cvt4(*(const float4*)bp);
            *(float4*)&Bs[brow * 20 + bq * 8 + 4] = cvt4(*(const float4*)(bp + 4));
        }
        __syncthreads();
        #pragma unroll
        for (int kk = 0; kk < 2; kk++) {
            const int co = c * 16 + kk * 8 + tig;
            float a[2][4];
            #pragma unroll
            for (int mt = 0; mt < 2; mt++) {
                const int ro = mw + mt * 16 + gid;
                a[mt][0] = As[ro * AS + co];
                a[mt][1] = As[(ro + 8) * AS + co];
                a[mt][2] = As[ro * AS + co + 4];
                a[mt][3] = As[(ro + 8) * AS + co + 4];
            }
            #pragma unroll
            for (int nt = 0; nt < 4; nt++) {
                const int n = jw + nt * 8 + gid;
                float b[2];
                b[0] = Bs[n * 20 + kk * 8 + tig];
                b[1] = Bs[n * 20 + kk * 8 + tig + 4];
                #pragma unroll
                for (int mt = 0; mt < 2; mt++) mma8(acc[mt][nt], a[mt], b);
            }
        }
        __syncthreads();
    }
    #pragma unroll
    for (int nt = 0; nt < 4; nt++) {
        const int col = bn + jw + nt * 8 + tig * 2;
        const float2 bb = *(const float2*)&bias[col];
        #pragma unroll
        for (int mt = 0; mt < 2; mt++)
            #pragma unroll
            for (int half = 0; half < 2; half++) {
                const int row = bm + mw + mt * 16 + gid + half * 8;
                float2 o;
                o.x = acc[mt][nt][half * 2]     + bb.x;
                o.y = acc[mt][nt][half * 2 + 1] + bb.y;
                *(float2*)&C[(size_t)row * N + col] = o;
            }
    }
}

// --------- Wh = last @ gat_intra_W ; s1 = Wh@a1 ; s2 = Wh@a2 ------------------
__global__ void __launch_bounds__(128) wh_intra_kernel(
    const float* __restrict__ W, const float* __restrict__ a)
{
    const int s = blockIdx.x, t = threadIdx.x;
    __shared__ float row[128];
    __shared__ float r1[128], r2[128];
    row[t] = g_short[(size_t)(s * WK + WK - 1) * 128 + t];
    __syncthreads();
    float acc = 0.f;
    #pragma unroll 4
    for (int k = 0; k < 128; k++) acc += row[k] * W[k * 128 + t];
    g_Wh[s * 128 + t] = acc;
    r1[t] = acc * a[t];
    r2[t] = acc * a[128 + t];
    __syncthreads();
    for (int off = 64; off; off >>= 1) {
        if (t < off) { r1[t] += r1[t + off]; r2[t] += r2[t + off]; }
        __syncthreads();
    }
    if (t == 0) { g_s1[s] = r1[0]; g_s2[s] = r2[0]; }
}

// ---------------- sector membership lists ------------------------------------
__global__ void __launch_bounds__(256) build_sectors(const int* __restrict__ sec)
{
    __shared__ int cnt[NSEC];
    const int tid = threadIdx.x;
    if (tid < NSEC) cnt[tid] = 0;
    __syncthreads();
    for (int s = tid; s < S_; s += 256) atomicAdd(&cnt[sec[s]], 1);
    __syncthreads();
    if (tid == 0) {
        int o = 0;
        for (int c = 0; c < NSEC; c++) { g_secoff[c] = o; o += cnt[c]; }
        g_secoff[NSEC] = o;
    }
    if (tid < NSEC) {
        int c = tid, p = 0;
        for (int q = 0; q < c; q++) p += cnt[q];
        for (int s = 0; s < S_; s++)
            if (sec[s] == c) g_secmem[p++] = s;
    }
}

// ---------------- intra GAT via sector lists ----------------------------------
__global__ void __launch_bounds__(128) gat_intra2(const int* __restrict__ sec)
{
    const int i = blockIdx.x, t = threadIdx.x;
    __shared__ int   mem[S_];
    __shared__ float s2m[S_];
    __shared__ float wm[S_];
    __shared__ float rm[128], rz[128];
    const int c = sec[i];
    const int base = g_secoff[c];
    const int n = g_secoff[c + 1] - base;
    for (int j = t; j < n; j += 128) {
        int idx = g_secmem[base + j];
        mem[j] = idx;
        s2m[j] = g_s2[idx];
    }
    __syncthreads();
    const float s1i = g_s1[i];
    float lm = -INFINITY, lz = 0.f;
    for (int j = t; j < n; j += 128) {
        float e = s1i + s2m[j];
        e = e > 0.f ? e : ALPHA * e;
        float mn = fmaxf(lm, e);
        lz = lz * expf(lm - mn) + expf(e - mn);
        lm = mn;
    }
    rm[t] = lm; rz[t] = lz;
    __syncthreads();
    for (int off = 64; off; off >>= 1) {
        if (t < off) {
            float m1 = rm[t], z1 = rz[t], m2 = rm[t + off], z2 = rz[t + off];
            float mn = fmaxf(m1, m2);
            float z = 0.f;
            if (z1 > 0.f) z += z1 * expf(m1 - mn);
            if (z2 > 0.f) z += z2 * expf(m2 - mn);
            rm[t] = mn; rz[t] = z;
        }
        __syncthreads();
    }
    const float Mv = rm[0], Zi = 1.f / rz[0];
    __syncthreads();
    for (int j = t; j < n; j += 128) {
        float e = s1i + s2m[j];
        e = e > 0.f ? e : ALPHA * e;
        wm[j] = expf(e - Mv) * Zi;
    }
    __syncthreads();
    float acc = 0.f;
    for (int j = 0; j < n; j++)
        acc += wm[j] * g_Wh[mem[j] * 128 + t];
    g_intra[i * 128 + t] = acc > 0.f ? acc : expf(acc) - 1.f;
}

// ---------------- lg: single-step GRU with h0=0 (gh = bhh) --------------------
__global__ void __launch_bounds__(256) lg_kernel(const float* __restrict__ bhh)
{
    int idx = blockIdx.x * 256 + threadIdx.x;
    if (idx >= S_ * 128) return;
    int s = idx >> 7, j = idx & 127;
    const float* gp = g_gig + (size_t)s * G3;
    float r = sigf(gp[j] + bhh[j]);
    float z = sigf(gp[128 + j] + bhh[128 + j]);
    float n = tanhf(gp[256 + j] + r * bhh[256 + j]);
    g_lg[idx] = (1.f - z) * n;
}

// ---------------- sector mean of lg ------------------------------------------
__global__ void __launch_bounds__(128) secmean2()
{
    const int c = blockIdx.x, t = threadIdx.x;
    const int base = g_secoff[c];
    const int n = g_secoff[c + 1] - base;
    float sum = 0.f;
    for (int j = 0; j < n; j++)
        sum += g_lg[g_secmem[base + j] * 128 + t];
    g_sec[c * 128 + t] = sum / fmaxf((float)n, 1.f);
}

// ---------------- inter GAT (16x16, exact NEG semantics) ----------------------
__global__ void __launch_bounds__(256) gat_inter_kernel(
    const int* __restrict__ adj, const float* __restrict__ W,
    const float* __restrict__ a)
{
    const int tid = threadIdx.x;
    __shared__ float Whs[NSEC * 128];
    __shared__ float s1g[NSEC], s2g[NSEC];
    __shared__ float att[NSEC * NSEC];
    for (int idx = tid; idx < NSEC * 128; idx += 256) {
        int i = idx >> 7, n = idx & 127;
        float acc = 0.f;
        for (int k = 0; k < 128; k++) acc += g_sec[i * 128 + k] * W[k * 128 + n];
        Whs[idx] = acc;
    }
    __syncthreads();
    if (tid < 32) {
        int i = tid & 15, which = tid >> 4;
        float acc = 0.f;
        for (int n = 0; n < 128; n++) acc += Whs[i * 128 + n] * a[which * 128 + n];
        if (which == 0) s1g[i] = acc; else s2g[i] = acc;
    }
    __syncthreads();
    if (tid < NSEC) {
        int i = tid;
        float e[NSEC];
        float mv = -INFINITY;
        for (int j = 0; j < NSEC; j++) {
            float v = s1g[i] + s2g[j];
            v = v > 0.f ? v : ALPHA * v;
            e[j] = (adj[i * NSEC + j] > 0) ? v : NEGV;
            mv = fmaxf(mv, e[j]);
        }
        float z = 0.f;
        for (int j = 0; j < NSEC; j++) { e[j] = expf(e[j] - mv); z += e[j]; }
        float zi = 1.f / z;
        for (int j = 0; j < NSEC; j++) att[i * NSEC + j] = e[j] * zi;
    }
    __syncthreads();
    for (int idx = tid; idx < NSEC * 128; idx += 256) {
        int i = idx >> 7, n = idx & 127;
        float acc = 0.f;
        #pragma unroll
        for (int j = 0; j < NSEC; j++) acc += att[i * NSEC + j] * Whs[j * 128 + n];
        g_secout[idx] = acc > 0.f ? acc : expf(acc) - 1.f;
    }
}

// ---------------- fusion + heads ---------------------------------------------
__global__ void __launch_bounds__(128) fused_kernel(
    const int* __restrict__ sec,
    const float* __restrict__ fw, const float* __restrict__ fb,
    const float* __restrict__ rw, const float* __restrict__ rb,
    const float* __restrict__ mw, const float* __restrict__ mb,
    float* __restrict__ out)
{
    const int s = blockIdx.x, t = threadIdx.x;
    __shared__ float cat[G3];
    __shared__ float r1[128], r2[128];
    cat[t]       = g_lg[s * 128 + t];
    cat[128 + t] = g_la[s * 128 + t];
    cat[256 + t] = g_secout[sec[s] * 128 + t];
    __syncthreads();
    float f = fb[t];
    #pragma unroll 4
    for (int k = 0; k < G3; k++) f += cat[k] * fw[k * 128 + t];
    r1[t] = f * rw[t];
    r2[t] = f * mw[t];
    __syncthreads();
    for (int off = 64; off; off >>= 1) {
        if (t < off) { r1[t] += r1[t + off]; r2[t] += r2[t + off]; }
        __syncthreads();
    }
    if (t == 0) {
        out[s]      = r1[0] + rb[0];
        out[S_ + s] = sigf(r2[0] + mb[0]);
    }
}

// ---------------- launch -----------------------------------------------------
extern "C" void kernel_launch(void* const* d_in, const int* in_sizes, int n_in,
                              void* d_out, int out_size)
{
    const float* x     = (const float*)d_in[0];
    const int*   sec   = (const int*)  d_in[1];
    const int*   adj   = (const int*)  d_in[2];
    const float* g1Wih = (const float*)d_in[3];
    const float* g1Whh = (const float*)d_in[4];
    const float* g1bih = (const float*)d_in[5];
    const float* g1bhh = (const float*)d_in[6];
    const float* a1w   = (const float*)d_in[7];
    const float* a1b   = (const float*)d_in[8];
    const float* giW   = (const float*)d_in[9];
    const float* gintra_a = (const float*)d_in[10];
    const float* ggWih = (const float*)d_in[11];
    const float* ggbih = (const float*)d_in[13];
    const float* ggbhh = (const float*)d_in[14];
    const float* gaWih = (const float*)d_in[17];
    const float* gaWhh = (const float*)d_in[18];
    const float* gabih = (const float*)d_in[19];
    const float* gabhh = (const float*)d_in[20];
    const float* aaw   = (const float*)d_in[21];
    const float* aab   = (const float*)d_in[22];
    const float* gintW = (const float*)d_in[23];
    const float* ginter_a = (const float*)d_in[24];
    const float* fw    = (const float*)d_in[25];
    const float* fb    = (const float*)d_in[26];
    const float* rw    = (const float*)d_in[27];
    const float* rb    = (const float*)d_in[28];
    const float* mw    = (const float*)d_in[29];
    const float* mb    = (const float*)d_in[30];
    float* out = (float*)d_out;

    float *p_short, *p_intra, *p_gig, *p_la;
    cudaGetSymbolAddress((void**)&p_short, g_short);
    cudaGetSymbolAddress((void**)&p_intra, g_intra);
    cudaGetSymbolAddress((void**)&p_gig,   g_gig);
    cudaGetSymbolAddress((void**)&p_la,    g_la);

    const int sm1 = 176128;
    const int sm2 = 225152;
    cudaFuncSetAttribute(gru1_fused, cudaFuncAttributeMaxDynamicSharedMemorySize, sm1);
    cudaFuncSetAttribute(la_fused,   cudaFuncAttributeMaxDynamicSharedMemorySize, sm2);

    cudaStream_t s2;
    cudaStreamCreateWithFlags(&s2, cudaStreamNonBlocking);
    cudaEvent_t e1, e2;
    cudaEventCreateWithFlags(&e1, cudaEventDisableTiming);
    cudaEventCreateWithFlags(&e2, cudaEventDisableTiming);

    build_sectors<<<1, 256>>>(sec);
    prep1<<<72, 256>>>(g1Whh, g1Wih, g1bih, g1bhh);
    prepa<<<128, 256, 0, s2>>>(gaWhh, gaWih, gabih, gabhh);  // overlaps gru1

    gru1_fused<<<148, 512, sm1>>>(x, a1w, a1b, p_short);      // persistent

    cudaEventRecord(e1, 0);
    cudaStreamWaitEvent(s2, e1, 0);
    la_fused<<<S_ / 16, 512, sm2, s2>>>(p_short, aaw, aab, p_la);

    wh_intra_kernel<<<S_, 128>>>(giW, gintra_a);
    gat_intra2<<<S_, 128>>>(sec);
    tgemm<<<dim3(G3 / 128, S_ / 64), 256>>>(p_intra, ggWih, ggbih, p_gig, S_, G3, EE);
    lg_kernel<<<(S_ * 128 + 255) / 256, 256>>>(ggbhh);
    secmean2<<<NSEC, 128>>>();
    gat_inter_kernel<<<1, 256>>>(adj, gintW, ginter_a);

    cudaEventRecord(e2, s2);
    cudaStreamWaitEvent(0, e2, 0);
    fused_kernel<<<S_, 128>>>(sec, fw, fb, rw, rb, mw, mb, out);

    (void)in_sizes; (void)n_in; (void)out_size;
}